// round 11
// baseline (speedup 1.0000x reference)
#include <cuda_runtime.h>
#include <cuda_fp16.h>
#include <math.h>
#include <stdint.h>

#define S_LEN 4096
#define NH 8
#define NKV 4
#define HD 256

// ---------------- scratch (allocation-free device globals) -----------------
__device__ __half g_q[(size_t)NH * S_LEN * HD];     // [h][s][d] fp16
__device__ __half g_k[(size_t)NKV * S_LEN * HD];    // [h][s][d] fp16
__device__ __half g_vt[(size_t)NKV * HD * S_LEN];   // [h][d][s] fp16 (transposed)
__device__ __half g_attn[(size_t)S_LEN * 2048];     // [s][h*HD+d] fp16
__device__ __half g_ah[(size_t)S_LEN * 2048];       // hs fp16
__device__ __half g_wqt[(size_t)2048 * 2048];       // weights [N][K] fp16
__device__ __half g_wkt[(size_t)1024 * 2048];
__device__ __half g_wvt[(size_t)1024 * 2048];
__device__ __half g_wot[(size_t)2048 * 2048];
__device__ double g_invd[128];                      // rope inv_freq table
__device__ int    g_ctr;                            // attn work counter

__device__ __forceinline__ uint32_t cvta_shared(const void* p) {
    uint32_t a;
    asm("{ .reg .u64 t; cvta.to.shared.u64 t, %1; cvt.u32.u64 %0, t; }"
        : "=r"(a) : "l"(p));
    return a;
}

__device__ __forceinline__ void cp16(uint32_t dst, const void* src) {
    asm volatile("cp.async.cg.shared.global [%0], [%1], 16;"
                 :: "r"(dst), "l"(src));
}
#define CP_COMMIT() asm volatile("cp.async.commit_group;")
#define CP_WAIT0()  asm volatile("cp.async.wait_group 0;")
#define CP_WAIT1()  asm volatile("cp.async.wait_group 1;")

#define MMA_F16(C, A, B0, B1)                                               \
    asm volatile(                                                           \
        "mma.sync.aligned.m16n8k16.row.col.f32.f16.f16.f32 "                \
        "{%0,%1,%2,%3}, {%4,%5,%6,%7}, {%8,%9}, {%0,%1,%2,%3};"             \
        : "+f"((C)[0]), "+f"((C)[1]), "+f"((C)[2]), "+f"((C)[3])            \
        : "r"((A)[0]), "r"((A)[1]), "r"((A)[2]), "r"((A)[3]),               \
          "r"(B0), "r"(B1))

__device__ __forceinline__ uint32_t pack2(float a, float b) {
    __half2 h = __floats2half2_rn(a, b);
    return *(uint32_t*)&h;
}

// ---------------------------------------------------------------------------
// Tiny prepass: inv_freq table (one fp64 exp per frequency, once).
// ---------------------------------------------------------------------------
__global__ void invd_kernel()
{
    int i = threadIdx.x;
    g_invd[i] = exp(-(double)i * (9.210340371976184 / 128.0));
}

// ---------------------------------------------------------------------------
// Prepass: fp32 -> fp16 (rn), 8 elems/thread.
// ---------------------------------------------------------------------------
__global__ void tohalf_kernel(const float* __restrict__ src,
                              __half* __restrict__ dst, int n8)
{
    int i = blockIdx.x * blockDim.x + threadIdx.x;
    if (i >= n8) return;
    float4 a = ((const float4*)src)[i * 2];
    float4 b = ((const float4*)src)[i * 2 + 1];
    uint4 o;
    o.x = pack2(a.x, a.y); o.y = pack2(a.z, a.w);
    o.z = pack2(b.x, b.y); o.w = pack2(b.z, b.w);
    ((uint4*)dst)[i] = o;
}

// ---------------------------------------------------------------------------
// Prepass: transpose + fp16 all four weights in ONE launch.
// ---------------------------------------------------------------------------
__global__ void thalf_all_kernel(const float* __restrict__ wq,
                                 const float* __restrict__ wk,
                                 const float* __restrict__ wv,
                                 const float* __restrict__ wo,
                                 __half* __restrict__ wqt,
                                 __half* __restrict__ wkt,
                                 __half* __restrict__ wvt,
                                 __half* __restrict__ wot)
{
    __shared__ float t[32][33];
    const int bx = blockIdx.x;
    const float* W;
    __half* Wt;
    int N, n0;
    if (bx < 64)       { W = wq; Wt = wqt; N = 2048; n0 = bx * 32; }
    else if (bx < 96)  { W = wk; Wt = wkt; N = 1024; n0 = (bx - 64) * 32; }
    else if (bx < 128) { W = wv; Wt = wvt; N = 1024; n0 = (bx - 96) * 32; }
    else               { W = wo; Wt = wot; N = 2048; n0 = (bx - 128) * 32; }
    const int k0 = blockIdx.y * 32;
    const int tx = threadIdx.x, ty = threadIdx.y;
#pragma unroll
    for (int j = 0; j < 4; j++)
        t[ty + 8 * j][tx] = W[(size_t)(k0 + ty + 8 * j) * N + n0 + tx];
    __syncthreads();
    const int nl = ty * 4 + (tx >> 3);
    const int kl = (tx & 7) * 4;
    uint2 o;
    o.x = pack2(t[kl + 0][nl], t[kl + 1][nl]);
    o.y = pack2(t[kl + 2][nl], t[kl + 3][nl]);
    *(uint2*)&Wt[(size_t)(n0 + nl) * 2048 + k0 + kl] = o;
}

// ---------------------------------------------------------------------------
// fp16 tensor-core GEMM (one barrier per k-chunk): C = A[M,2048] @ Wt^T.
// 128x128 CTA tile, BK=64, 8 warps (4m x 2n), cp.async double-buffered.
// ---------------------------------------------------------------------------
#define GH_PLANE 18432                   // 128 rows * 144 B
#define GH_STAGE (2 * GH_PLANE)
#define GH_SMEM  (2 * GH_STAGE)          // 73728 B

__global__ __launch_bounds__(256, 2) void gemm_h_kernel(
    const __half* __restrict__ A,
    const __half* __restrict__ B0t, const __half* __restrict__ B1t,
    const __half* __restrict__ B2t,
    __half* __restrict__ Cq, __half* __restrict__ Ck, __half* __restrict__ Cvt,
    float* __restrict__ Cplain, int merged)
{
    extern __shared__ char gsm[];
    const uint32_t smem_base = cvta_shared(gsm);

    const int tid  = threadIdx.x;
    const int lane = tid & 31;
    const int wid  = tid >> 5;
    const int wm   = (wid & 3) * 32;
    const int wn   = (wid >> 2) * 64;
    const int bm   = blockIdx.y * 128;
    const int bn   = blockIdx.x * 128;
    const int grp  = lane >> 2;
    const int qd   = lane & 3;

    const __half* Bt;
    int nb, head = 0, colb0 = 0, region = 0;
    if (merged) {
        if (bn < 2048)      { Bt = B0t; nb = bn;        region = 0; }
        else if (bn < 3072) { Bt = B1t; nb = bn - 2048; region = 1; }
        else                { Bt = B2t; nb = bn - 3072; region = 2; }
        head = nb >> 8;
        colb0 = nb & 255;
    } else {
        Bt = B0t; nb = bn;
    }

    auto load_stage = [&](int chunk, int st) {
        const int k0 = chunk * 64;
        const uint32_t sb = smem_base + st * GH_STAGE;
#pragma unroll
        for (int p = 0; p < 4; p++) {
            int idx = tid + p * 256;
            int row = idx >> 3, c = idx & 7;
            cp16(sb + row * 144 + c * 16,
                 &A[(size_t)(bm + row) * 2048 + k0 + c * 8]);
            cp16(sb + GH_PLANE + row * 144 + c * 16,
                 &Bt[(size_t)(nb + row) * 2048 + k0 + c * 8]);
        }
        CP_COMMIT();
    };

    float c[2][8][4];
#pragma unroll
    for (int mf = 0; mf < 2; mf++)
#pragma unroll
        for (int nt = 0; nt < 8; nt++)
#pragma unroll
            for (int r = 0; r < 4; r++) c[mf][nt][r] = 0.f;

    load_stage(0, 0);

    for (int i = 0; i < 32; i++) {
        const int st = i & 1;
        CP_WAIT0();
        __syncthreads();   // covers both data-ready and stage-reuse safety
        if (i + 1 < 32) load_stage(i + 1, st ^ 1);

        const uint32_t* Asu = (const uint32_t*)(gsm + st * GH_STAGE);
        const uint32_t* Bsu = (const uint32_t*)(gsm + st * GH_STAGE + GH_PLANE);
#pragma unroll
        for (int s = 0; s < 4; s++) {
            const int kc = s * 8 + qd;
            uint32_t a[2][4];
#pragma unroll
            for (int mf = 0; mf < 2; mf++) {
                const int R = wm + mf * 16 + grp;
                a[mf][0] = Asu[R * 36 + kc];
                a[mf][1] = Asu[(R + 8) * 36 + kc];
                a[mf][2] = Asu[R * 36 + kc + 4];
                a[mf][3] = Asu[(R + 8) * 36 + kc + 4];
            }
#pragma unroll
            for (int nt = 0; nt < 8; nt++) {
                const int nc = wn + nt * 8 + grp;
                uint32_t b0 = Bsu[nc * 36 + kc];
                uint32_t b1 = Bsu[nc * 36 + kc + 4];
#pragma unroll
                for (int mf = 0; mf < 2; mf++)
                    MMA_F16(c[mf][nt], a[mf], b0, b1);
            }
        }
    }

    const int m0 = bm + wm + grp;
    const int n0 = wn + 2 * qd;
    if (merged) {
        if (region < 2) {
            __half* Cp = (region == 0) ? Cq : Ck;
            const size_t hbase = (size_t)head * ((size_t)S_LEN * HD) + colb0;
#pragma unroll
            for (int mf = 0; mf < 2; mf++)
#pragma unroll
                for (int nt = 0; nt < 8; nt++) {
                    int m = m0 + mf * 16;
                    int ncol = n0 + nt * 8;
                    *(uint32_t*)&Cp[hbase + (size_t)m * HD + ncol] =
                        pack2(c[mf][nt][0], c[mf][nt][1]);
                    *(uint32_t*)&Cp[hbase + (size_t)(m + 8) * HD + ncol] =
                        pack2(c[mf][nt][2], c[mf][nt][3]);
                }
        } else {
            const size_t vbase = (size_t)head * ((size_t)HD * S_LEN);
#pragma unroll
            for (int mf = 0; mf < 2; mf++)
#pragma unroll
                for (int nt = 0; nt < 8; nt++) {
                    int m = m0 + mf * 16;
                    int d = colb0 + n0 + nt * 8;
                    Cvt[vbase + (size_t)d * S_LEN + m]           = __float2half_rn(c[mf][nt][0]);
                    Cvt[vbase + (size_t)(d + 1) * S_LEN + m]     = __float2half_rn(c[mf][nt][1]);
                    Cvt[vbase + (size_t)d * S_LEN + m + 8]       = __float2half_rn(c[mf][nt][2]);
                    Cvt[vbase + (size_t)(d + 1) * S_LEN + m + 8] = __float2half_rn(c[mf][nt][3]);
                }
        }
    } else {
#pragma unroll
        for (int mf = 0; mf < 2; mf++)
#pragma unroll
            for (int nt = 0; nt < 8; nt++) {
                int m = m0 + mf * 16;
                int n = bn + n0 + nt * 8;
                *(float2*)&Cplain[(size_t)m * 2048 + n] =
                    make_float2(c[mf][nt][0], c[mf][nt][1]);
                *(float2*)&Cplain[(size_t)(m + 8) * 2048 + n] =
                    make_float2(c[mf][nt][2], c[mf][nt][3]);
            }
    }
}

// ---------------------------------------------------------------------------
// RoPE on fp16 q/k. inv_freq from table; range reduction via DMUL (no DDIV,
// no per-thread fp64 exp). Thread 0 also resets the attention work counter.
// ---------------------------------------------------------------------------
__global__ void rope_kernel(const void* __restrict__ pos_raw)
{
    int idx = blockIdx.x * blockDim.x + threadIdx.x;
    if (idx == 0) g_ctr = 0;
    if (idx >= S_LEN * 128) return;
    int i = idx & 127;
    int s = idx >> 7;

    const int* p32 = (const int*)pos_raw;
    long long pll = (p32[1] == 0) ? ((const long long*)pos_raw)[s]
                                  : (long long)p32[s];
    float p = (float)pll;

    float f = (float)((double)p * g_invd[i]);   // fp32 freq like reference
    const double TWO_PI     = 6.283185307179586476925287;
    const double INV_TWO_PI = 0.15915494309189533576888;
    double r = (double)f;
    r -= TWO_PI * floor(r * INV_TWO_PI);
    float sv = sinf((float)r);
    float cv = cosf((float)r);

#pragma unroll
    for (int h = 0; h < NH; h++) {
        __half* base = g_q + ((size_t)h * S_LEN + s) * HD;
        float x1 = __half2float(base[i]), x2 = __half2float(base[i + 128]);
        base[i]       = __float2half_rn((x1 * cv - x2 * sv) * 0.0625f);
        base[i + 128] = __float2half_rn((x2 * cv + x1 * sv) * 0.0625f);
    }
#pragma unroll
    for (int h = 0; h < NKV; h++) {
        __half* base = g_k + ((size_t)h * S_LEN + s) * HD;
        float x1 = __half2float(base[i]), x2 = __half2float(base[i + 128]);
        base[i]       = __float2half_rn(x1 * cv - x2 * sv);
        base[i + 128] = __float2half_rn(x2 * cv + x1 * sv);
    }
}

// ---------------------------------------------------------------------------
// Persistent fp16 flash attention with dynamic LPT scheduling.
// 148 CTAs; 512 work items = (head, 64-row q-tile), grabbed in descending
// cost order (qt = 63 - t/8) via atomic counter. 8 warps (4m x 2 half):
// QK: warp rows wm..+16, k-cols wc*32..+32; PV: same rows, d-cols wc*128.
// In-register softmax; cross-warp max via hm smem; P fp16 in smem.
// Output fp16 [s][h*HD+d].
// ---------------------------------------------------------------------------
#define AQ_STR 132                        // uint32 per Q/K row (528 B)
#define AOFF_Q 0
#define AOFF_K 33792                      // 64*528
#define AOFF_V 67584                      // + 64*528
#define AOFF_P 104448                     // + 256*144
#define AOFF_M 113664                     // + 64*144
#define AOFF_L 114176                     // + 512
#define ATTN_SMEM 114688                  // + 512

__global__ __launch_bounds__(256) void attn_h_kernel()
{
    extern __shared__ char smn[];
    const uint32_t sb = cvta_shared(smn);
    const uint32_t* Qfu = (const uint32_t*)(smn + AOFF_Q);
    const uint32_t* Kfu = (const uint32_t*)(smn + AOFF_K);
    const uint32_t* Vtu = (const uint32_t*)(smn + AOFF_V);
    uint32_t* Ppu = (uint32_t*)(smn + AOFF_P);
    float* hm = (float*)(smn + AOFF_M);
    float* ll = (float*)(smn + AOFF_L);
    __shared__ int s_t;

    const int tid  = threadIdx.x;
    const int lane = tid & 31;
    const int wid  = tid >> 5;
    const int wm   = (wid & 3) * 16;
    const int wc   = wid >> 2;
    const int grp  = lane >> 2;
    const int qd   = lane & 3;
    const int R    = wm + grp;            // local row, slot0 (slot1 = R+8)

    const float LOG2E = 1.4426950408889634f;

    while (true) {
        if (tid == 0) s_t = atomicAdd(&g_ctr, 1);
        __syncthreads();
        const int t = s_t;
        if (t >= 512) break;
        const int qt = 63 - (t >> 3);
        const int h  = t & 7;
        const int hk = h >> 1;
        const int q0 = qt * 64;

        const __half* Qh  = g_q  + (size_t)h  * S_LEN * HD;
        const __half* Kh  = g_k  + (size_t)hk * S_LEN * HD;
        const __half* Vth = g_vt + (size_t)hk * HD * S_LEN;

        // stage Q (64 x 256 halves)
#pragma unroll
        for (int p = 0; p < 8; p++) {
            int idx = tid + p * 256;
            int row = idx >> 5, cc = idx & 31;
            cp16(sb + AOFF_Q + row * 528 + cc * 16,
                 &Qh[(size_t)(q0 + row) * HD + cc * 8]);
        }
        CP_COMMIT();

        float m_run[2] = {-3.0e38f, -3.0e38f};
        float l_run[2] = {0.f, 0.f};
        float o[16][4];
#pragma unroll
        for (int nt = 0; nt < 16; nt++)
#pragma unroll
            for (int r = 0; r < 4; r++) o[nt][r] = 0.f;

        for (int kb = 0; kb <= qt; kb++) {
            const int k0 = kb * 64;
            __syncthreads();   // guard K/V/P/hm reuse from previous k-block
            // K tile 64x256 halves
#pragma unroll
            for (int p = 0; p < 8; p++) {
                int idx = tid + p * 256;
                int row = idx >> 5, cc = idx & 31;
                cp16(sb + AOFF_K + row * 528 + cc * 16,
                     &Kh[(size_t)(k0 + row) * HD + cc * 8]);
            }
            CP_COMMIT();
            // Vt tile 256(d) x 64(s) halves
#pragma unroll
            for (int p = 0; p < 8; p++) {
                int idx = tid + p * 256;
                int row = idx >> 3, cc = idx & 7;
                cp16(sb + AOFF_V + row * 144 + cc * 16,
                     &Vth[(size_t)row * S_LEN + k0 + cc * 8]);
            }
            CP_COMMIT();
            CP_WAIT1();        // Q(first)/K ready; V may still fly
            __syncthreads();

            // ---- QK: rows wm..+16, cols wc*32..+32 ----
            float s[4][4];
#pragma unroll
            for (int nt = 0; nt < 4; nt++)
#pragma unroll
                for (int r = 0; r < 4; r++) s[nt][r] = 0.f;
#pragma unroll 4
            for (int ks = 0; ks < 16; ks++) {
                const int kc = ks * 8 + qd;
                uint32_t a[4];
                a[0] = Qfu[R * AQ_STR + kc];
                a[1] = Qfu[(R + 8) * AQ_STR + kc];
                a[2] = Qfu[R * AQ_STR + kc + 4];
                a[3] = Qfu[(R + 8) * AQ_STR + kc + 4];
#pragma unroll
                for (int nt = 0; nt < 4; nt++) {
                    const int nc = wc * 32 + nt * 8 + grp;
                    uint32_t b0 = Kfu[nc * AQ_STR + kc];
                    uint32_t b1 = Kfu[nc * AQ_STR + kc + 4];
                    MMA_F16(s[nt], a, b0, b1);
                }
            }

            // ---- softcap + causal + local row max ----
            float lm[2] = {-3.0e38f, -3.0e38f};
#pragma unroll
            for (int nt = 0; nt < 4; nt++)
#pragma unroll
                for (int cc = 0; cc < 4; cc++) {
                    float x = s[nt][cc];
                    float u = x * 0.02f;
                    float u2 = u * u;
                    float val = x * (1.f + u2 * (-0.333333333f +
                                  u2 * (0.133333333f + u2 * -0.053968254f)));
                    if (u2 > 0.1225f) val = 50.f * tanhf(u);
                    int kcol = k0 + wc * 32 + nt * 8 + 2 * qd + (cc & 1);
                    int qrow = q0 + R + (cc >> 1) * 8;
                    if (kcol > qrow) val = -1.0e30f;
                    s[nt][cc] = val;
                    int sl = cc >> 1;
                    lm[sl] = fmaxf(lm[sl], val);
                }
#pragma unroll
            for (int sl = 0; sl < 2; sl++) {
                lm[sl] = fmaxf(lm[sl], __shfl_xor_sync(0xffffffffu, lm[sl], 1));
                lm[sl] = fmaxf(lm[sl], __shfl_xor_sync(0xffffffffu, lm[sl], 2));
            }
            if (qd == 0) {
                hm[R * 2 + wc]       = lm[0];
                hm[(R + 8) * 2 + wc] = lm[1];
            }
            __syncthreads();   // hm partials visible

            // ---- combine max; exp; P; l ----
            float resc[2], ps[2];
#pragma unroll
            for (int sl = 0; sl < 2; sl++) {
                int rr = R + sl * 8;
                float om = fmaxf(hm[rr * 2], hm[rr * 2 + 1]);
                float mn = fmaxf(m_run[sl], om);
                resc[sl] = exp2f((m_run[sl] - mn) * LOG2E);
                m_run[sl] = mn;
                ps[sl] = 0.f;
            }
#pragma unroll
            for (int nt = 0; nt < 4; nt++) {
                float e0 = exp2f((s[nt][0] - m_run[0]) * LOG2E);
                float e1 = exp2f((s[nt][1] - m_run[0]) * LOG2E);
                float e2 = exp2f((s[nt][2] - m_run[1]) * LOG2E);
                float e3 = exp2f((s[nt][3] - m_run[1]) * LOG2E);
                ps[0] += e0 + e1;
                ps[1] += e2 + e3;
                Ppu[R * 36 + wc * 16 + nt * 4 + qd]       = pack2(e0, e1);
                Ppu[(R + 8) * 36 + wc * 16 + nt * 4 + qd] = pack2(e2, e3);
            }
#pragma unroll
            for (int sl = 0; sl < 2; sl++) {
                ps[sl] += __shfl_xor_sync(0xffffffffu, ps[sl], 1);
                ps[sl] += __shfl_xor_sync(0xffffffffu, ps[sl], 2);
                l_run[sl] = l_run[sl] * resc[sl] + ps[sl];
            }
#pragma unroll
            for (int nt = 0; nt < 16; nt++) {
                o[nt][0] *= resc[0]; o[nt][1] *= resc[0];
                o[nt][2] *= resc[1]; o[nt][3] *= resc[1];
            }
            CP_WAIT0();        // V ready
            __syncthreads();   // P + V visible

            // ---- PV: rows wm..+16, d-cols wc*128..+128 ----
#pragma unroll
            for (int s4 = 0; s4 < 4; s4++) {
                const int kc = s4 * 8 + qd;
                uint32_t a[4];
                a[0] = Ppu[R * 36 + kc];
                a[1] = Ppu[(R + 8) * 36 + kc];
                a[2] = Ppu[R * 36 + kc + 4];
                a[3] = Ppu[(R + 8) * 36 + kc + 4];
#pragma unroll
                for (int nt = 0; nt < 16; nt++) {
                    const int nc = wc * 128 + nt * 8 + grp;
                    uint32_t b0 = Vtu[nc * 36 + kc];
                    uint32_t b1 = Vtu[nc * 36 + kc + 4];
                    MMA_F16(o[nt], a, b0, b1);
                }
            }
        }

        // ---- epilogue: combine l halves, normalize, write fp16 ----
        if (qd == 0) {
            ll[R * 2 + wc]       = l_run[0];
            ll[(R + 8) * 2 + wc] = l_run[1];
        }
        __syncthreads();
        float i0 = 1.f / (ll[R * 2] + ll[R * 2 + 1]);
        float i1 = 1.f / (ll[(R + 8) * 2] + ll[(R + 8) * 2 + 1]);
#pragma unroll
        for (int nt = 0; nt < 16; nt++) {
            int col = h * HD + wc * 128 + nt * 8 + 2 * qd;
            *(uint32_t*)&g_attn[(size_t)(q0 + R) * 2048 + col] =
                pack2(o[nt][0] * i0, o[nt][1] * i0);
            *(uint32_t*)&g_attn[(size_t)(q0 + R + 8) * 2048 + col] =
                pack2(o[nt][2] * i1, o[nt][3] * i1);
        }
        __syncthreads();   // all done with ll (and smem) before next grab
    }
}

// ---------------------------------------------------------------------------
extern "C" void kernel_launch(void* const* d_in, const int* in_sizes, int n_in,
                              void* d_out, int out_size)
{
    const float* hs  = (const float*)d_in[0];
    // d_in[1] = attention_mask: pure causal (window >= S), recomputed in-kernel
    const void*  pos = d_in[2];
    const float* wq  = (const float*)d_in[3];
    const float* wk  = (const float*)d_in[4];
    const float* wv  = (const float*)d_in[5];
    const float* wo  = (const float*)d_in[6];
    float* out = (float*)d_out;

    __half *pq, *pk, *pvt, *pa, *pah, *pwqt, *pwkt, *pwvt, *pwot;
    cudaGetSymbolAddress((void**)&pq,   g_q);
    cudaGetSymbolAddress((void**)&pk,   g_k);
    cudaGetSymbolAddress((void**)&pvt,  g_vt);
    cudaGetSymbolAddress((void**)&pa,   g_attn);
    cudaGetSymbolAddress((void**)&pah,  g_ah);
    cudaGetSymbolAddress((void**)&pwqt, g_wqt);
    cudaGetSymbolAddress((void**)&pwkt, g_wkt);
    cudaGetSymbolAddress((void**)&pwvt, g_wvt);
    cudaGetSymbolAddress((void**)&pwot, g_wot);

    cudaFuncSetAttribute(gemm_h_kernel,
                         cudaFuncAttributeMaxDynamicSharedMemorySize, GH_SMEM);
    cudaFuncSetAttribute(attn_h_kernel,
                         cudaFuncAttributeMaxDynamicSharedMemorySize, ATTN_SMEM);

    const int n8 = (S_LEN * 2048) / 8;
    dim3 tb(32, 8);

    // prepasses
    invd_kernel<<<1, 128>>>();
    tohalf_kernel<<<(n8 + 255) / 256, 256>>>(hs, pah, n8);
    thalf_all_kernel<<<dim3(192, 64), tb>>>(wq, wk, wv, wo,
                                            pwqt, pwkt, pwvt, pwot);
    // fused QKV projection
    gemm_h_kernel<<<dim3(32, 32), 256, GH_SMEM>>>(
        pah, pwqt, pwkt, pwvt, pq, pk, pvt, nullptr, 1);
    // RoPE (+ scaling fold + attn counter reset)
    rope_kernel<<<(S_LEN * 128) / 256, 256>>>(pos);
    // persistent causal flash attention with tanh softcap
    attn_h_kernel<<<148, 256, ATTN_SMEM>>>();
    // output projection (reads fp16 attention output directly)
    gemm_h_kernel<<<dim3(16, 32), 256, GH_SMEM>>>(
        pa, pwot, nullptr, nullptr, nullptr, nullptr, nullptr, out, 0);
}

// round 12
// speedup vs baseline: 1.6057x; 1.6057x over previous
#include <cuda_runtime.h>
#include <cuda_fp16.h>
#include <math.h>
#include <stdint.h>

#define S_LEN 4096
#define NH 8
#define NKV 4
#define HD 256

// ---------------- scratch (allocation-free device globals) -----------------
__device__ __half g_q[(size_t)NH * S_LEN * HD];     // [h][s][d] fp16
__device__ __half g_k[(size_t)NKV * S_LEN * HD];    // [h][s][d] fp16
__device__ __half g_vt[(size_t)NKV * HD * S_LEN];   // [h][d][s] fp16 (transposed)
__device__ __half g_attn[(size_t)S_LEN * 2048];     // [s][h*HD+d] fp16
__device__ __half g_ah[(size_t)S_LEN * 2048];       // hs fp16
__device__ __half g_wqt[(size_t)2048 * 2048];       // weights [N][K] fp16
__device__ __half g_wkt[(size_t)1024 * 2048];
__device__ __half g_wvt[(size_t)1024 * 2048];
__device__ __half g_wot[(size_t)2048 * 2048];
__device__ double g_invd[128];                      // rope inv_freq table

__device__ __forceinline__ uint32_t cvta_shared(const void* p) {
    uint32_t a;
    asm("{ .reg .u64 t; cvta.to.shared.u64 t, %1; cvt.u32.u64 %0, t; }"
        : "=r"(a) : "l"(p));
    return a;
}

__device__ __forceinline__ void cp16(uint32_t dst, const void* src) {
    asm volatile("cp.async.cg.shared.global [%0], [%1], 16;"
                 :: "r"(dst), "l"(src));
}
#define CP_COMMIT() asm volatile("cp.async.commit_group;")
#define CP_WAIT0()  asm volatile("cp.async.wait_group 0;")
#define CP_WAIT1()  asm volatile("cp.async.wait_group 1;")

#define MMA_F16(C, A, B0, B1)                                               \
    asm volatile(                                                           \
        "mma.sync.aligned.m16n8k16.row.col.f32.f16.f16.f32 "                \
        "{%0,%1,%2,%3}, {%4,%5,%6,%7}, {%8,%9}, {%0,%1,%2,%3};"             \
        : "+f"((C)[0]), "+f"((C)[1]), "+f"((C)[2]), "+f"((C)[3])            \
        : "r"((A)[0]), "r"((A)[1]), "r"((A)[2]), "r"((A)[3]),               \
          "r"(B0), "r"(B1))

__device__ __forceinline__ uint32_t pack2(float a, float b) {
    __half2 h = __floats2half2_rn(a, b);
    return *(uint32_t*)&h;
}

// ---------------------------------------------------------------------------
// Tiny prepass: inv_freq table (one fp64 exp per frequency, once).
// ---------------------------------------------------------------------------
__global__ void invd_kernel()
{
    int i = threadIdx.x;
    g_invd[i] = exp(-(double)i * (9.210340371976184 / 128.0));
}

// ---------------------------------------------------------------------------
// Prepass: fp32 -> fp16 (rn), 8 elems/thread.
// ---------------------------------------------------------------------------
__global__ void tohalf_kernel(const float* __restrict__ src,
                              __half* __restrict__ dst, int n8)
{
    int i = blockIdx.x * blockDim.x + threadIdx.x;
    if (i >= n8) return;
    float4 a = ((const float4*)src)[i * 2];
    float4 b = ((const float4*)src)[i * 2 + 1];
    uint4 o;
    o.x = pack2(a.x, a.y); o.y = pack2(a.z, a.w);
    o.z = pack2(b.x, b.y); o.w = pack2(b.z, b.w);
    ((uint4*)dst)[i] = o;
}

// ---------------------------------------------------------------------------
// Prepass: transpose + fp16 all four weights in ONE launch.
// ---------------------------------------------------------------------------
__global__ void thalf_all_kernel(const float* __restrict__ wq,
                                 const float* __restrict__ wk,
                                 const float* __restrict__ wv,
                                 const float* __restrict__ wo,
                                 __half* __restrict__ wqt,
                                 __half* __restrict__ wkt,
                                 __half* __restrict__ wvt,
                                 __half* __restrict__ wot)
{
    __shared__ float t[32][33];
    const int bx = blockIdx.x;
    const float* W;
    __half* Wt;
    int N, n0;
    if (bx < 64)       { W = wq; Wt = wqt; N = 2048; n0 = bx * 32; }
    else if (bx < 96)  { W = wk; Wt = wkt; N = 1024; n0 = (bx - 64) * 32; }
    else if (bx < 128) { W = wv; Wt = wvt; N = 1024; n0 = (bx - 96) * 32; }
    else               { W = wo; Wt = wot; N = 2048; n0 = (bx - 128) * 32; }
    const int k0 = blockIdx.y * 32;
    const int tx = threadIdx.x, ty = threadIdx.y;
#pragma unroll
    for (int j = 0; j < 4; j++)
        t[ty + 8 * j][tx] = W[(size_t)(k0 + ty + 8 * j) * N + n0 + tx];
    __syncthreads();
    const int nl = ty * 4 + (tx >> 3);
    const int kl = (tx & 7) * 4;
    uint2 o;
    o.x = pack2(t[kl + 0][nl], t[kl + 1][nl]);
    o.y = pack2(t[kl + 2][nl], t[kl + 3][nl]);
    *(uint2*)&Wt[(size_t)(n0 + nl) * 2048 + k0 + kl] = o;
}

// ---------------------------------------------------------------------------
// fp16 tensor-core GEMM: C[M,N] = A[M,2048] @ Wt[N,2048]^T, m16n8k16,
// 128x128 CTA tile, BK=64, 8 warps (4m x 2n), cp.async double-buffered.
// merged=1: fused QKV. bn<2048 -> q; <3072 -> k; else v transposed [h][d][s].
// merged=0: plain fp32 out [M,2048].
// ---------------------------------------------------------------------------
#define GH_PLANE 18432                   // 128 rows * 144 B
#define GH_STAGE (2 * GH_PLANE)
#define GH_SMEM  (2 * GH_STAGE)          // 73728 B

__global__ __launch_bounds__(256, 2) void gemm_h_kernel(
    const __half* __restrict__ A,
    const __half* __restrict__ B0t, const __half* __restrict__ B1t,
    const __half* __restrict__ B2t,
    __half* __restrict__ Cq, __half* __restrict__ Ck, __half* __restrict__ Cvt,
    float* __restrict__ Cplain, int merged)
{
    extern __shared__ char gsm[];
    const uint32_t smem_base = cvta_shared(gsm);

    const int tid  = threadIdx.x;
    const int lane = tid & 31;
    const int wid  = tid >> 5;
    const int wm   = (wid & 3) * 32;
    const int wn   = (wid >> 2) * 64;
    const int bm   = blockIdx.y * 128;
    const int bn   = blockIdx.x * 128;
    const int grp  = lane >> 2;
    const int qd   = lane & 3;

    const __half* Bt;
    int nb, head = 0, colb0 = 0, region = 0;
    if (merged) {
        if (bn < 2048)      { Bt = B0t; nb = bn;        region = 0; }
        else if (bn < 3072) { Bt = B1t; nb = bn - 2048; region = 1; }
        else                { Bt = B2t; nb = bn - 3072; region = 2; }
        head = nb >> 8;
        colb0 = nb & 255;
    } else {
        Bt = B0t; nb = bn;
    }

    auto load_stage = [&](int chunk, int st) {
        const int k0 = chunk * 64;
        const uint32_t sb = smem_base + st * GH_STAGE;
#pragma unroll
        for (int p = 0; p < 4; p++) {
            int idx = tid + p * 256;
            int row = idx >> 3, c = idx & 7;
            cp16(sb + row * 144 + c * 16,
                 &A[(size_t)(bm + row) * 2048 + k0 + c * 8]);
            cp16(sb + GH_PLANE + row * 144 + c * 16,
                 &Bt[(size_t)(nb + row) * 2048 + k0 + c * 8]);
        }
        CP_COMMIT();
    };

    float c[2][8][4];
#pragma unroll
    for (int mf = 0; mf < 2; mf++)
#pragma unroll
        for (int nt = 0; nt < 8; nt++)
#pragma unroll
            for (int r = 0; r < 4; r++) c[mf][nt][r] = 0.f;

    load_stage(0, 0);

    for (int i = 0; i < 32; i++) {
        const int st = i & 1;
        CP_WAIT0();
        __syncthreads();
        if (i + 1 < 32) load_stage(i + 1, st ^ 1);

        const uint32_t* Asu = (const uint32_t*)(gsm + st * GH_STAGE);
        const uint32_t* Bsu = (const uint32_t*)(gsm + st * GH_STAGE + GH_PLANE);
#pragma unroll
        for (int s = 0; s < 4; s++) {
            const int kc = s * 8 + qd;
            uint32_t a[2][4];
#pragma unroll
            for (int mf = 0; mf < 2; mf++) {
                const int R = wm + mf * 16 + grp;
                a[mf][0] = Asu[R * 36 + kc];
                a[mf][1] = Asu[(R + 8) * 36 + kc];
                a[mf][2] = Asu[R * 36 + kc + 4];
                a[mf][3] = Asu[(R + 8) * 36 + kc + 4];
            }
#pragma unroll
            for (int nt = 0; nt < 8; nt++) {
                const int nc = wn + nt * 8 + grp;
                uint32_t b0 = Bsu[nc * 36 + kc];
                uint32_t b1 = Bsu[nc * 36 + kc + 4];
#pragma unroll
                for (int mf = 0; mf < 2; mf++)
                    MMA_F16(c[mf][nt], a[mf], b0, b1);
            }
        }
        __syncthreads();
    }

    const int m0 = bm + wm + grp;
    const int n0 = wn + 2 * qd;
    if (merged) {
        if (region < 2) {
            __half* Cp = (region == 0) ? Cq : Ck;
            const size_t hbase = (size_t)head * ((size_t)S_LEN * HD) + colb0;
#pragma unroll
            for (int mf = 0; mf < 2; mf++)
#pragma unroll
                for (int nt = 0; nt < 8; nt++) {
                    int m = m0 + mf * 16;
                    int ncol = n0 + nt * 8;
                    *(uint32_t*)&Cp[hbase + (size_t)m * HD + ncol] =
                        pack2(c[mf][nt][0], c[mf][nt][1]);
                    *(uint32_t*)&Cp[hbase + (size_t)(m + 8) * HD + ncol] =
                        pack2(c[mf][nt][2], c[mf][nt][3]);
                }
        } else {
            const size_t vbase = (size_t)head * ((size_t)HD * S_LEN);
#pragma unroll
            for (int mf = 0; mf < 2; mf++)
#pragma unroll
                for (int nt = 0; nt < 8; nt++) {
                    int m = m0 + mf * 16;
                    int d = colb0 + n0 + nt * 8;
                    Cvt[vbase + (size_t)d * S_LEN + m]           = __float2half_rn(c[mf][nt][0]);
                    Cvt[vbase + (size_t)(d + 1) * S_LEN + m]     = __float2half_rn(c[mf][nt][1]);
                    Cvt[vbase + (size_t)d * S_LEN + m + 8]       = __float2half_rn(c[mf][nt][2]);
                    Cvt[vbase + (size_t)(d + 1) * S_LEN + m + 8] = __float2half_rn(c[mf][nt][3]);
                }
        }
    } else {
#pragma unroll
        for (int mf = 0; mf < 2; mf++)
#pragma unroll
            for (int nt = 0; nt < 8; nt++) {
                int m = m0 + mf * 16;
                int n = bn + n0 + nt * 8;
                *(float2*)&Cplain[(size_t)m * 2048 + n] =
                    make_float2(c[mf][nt][0], c[mf][nt][1]);
                *(float2*)&Cplain[(size_t)(m + 8) * 2048 + n] =
                    make_float2(c[mf][nt][2], c[mf][nt][3]);
            }
    }
}

// ---------------------------------------------------------------------------
// RoPE on fp16 q/k. inv_freq from table; range reduction via DMUL (no DDIV,
// no per-thread fp64 exp).
// ---------------------------------------------------------------------------
__global__ void rope_kernel(const void* __restrict__ pos_raw)
{
    int idx = blockIdx.x * blockDim.x + threadIdx.x;
    if (idx >= S_LEN * 128) return;
    int i = idx & 127;
    int s = idx >> 7;

    const int* p32 = (const int*)pos_raw;
    long long pll = (p32[1] == 0) ? ((const long long*)pos_raw)[s]
                                  : (long long)p32[s];
    float p = (float)pll;

    float f = (float)((double)p * g_invd[i]);   // fp32 freq like reference
    const double TWO_PI     = 6.283185307179586476925287;
    const double INV_TWO_PI = 0.15915494309189533576888;
    double r = (double)f;
    r -= TWO_PI * floor(r * INV_TWO_PI);
    float sv = sinf((float)r);
    float cv = cosf((float)r);

#pragma unroll
    for (int h = 0; h < NH; h++) {
        __half* base = g_q + ((size_t)h * S_LEN + s) * HD;
        float x1 = __half2float(base[i]), x2 = __half2float(base[i + 128]);
        base[i]       = __float2half_rn((x1 * cv - x2 * sv) * 0.0625f);
        base[i + 128] = __float2half_rn((x2 * cv + x1 * sv) * 0.0625f);
    }
#pragma unroll
    for (int h = 0; h < NKV; h++) {
        __half* base = g_k + ((size_t)h * S_LEN + s) * HD;
        float x1 = __half2float(base[i]), x2 = __half2float(base[i + 128]);
        base[i]       = __float2half_rn(x1 * cv - x2 * sv);
        base[i + 128] = __float2half_rn(x2 * cv + x1 * sv);
    }
}

// ---------------------------------------------------------------------------
// fp16 flash attention, in-register softmax on QK fragments (R10 winner).
// Grid (16, 8) = 128 blocks, block = q-tiles qt & 31-qt (128 rows each),
// 66 uniform k-blocks of 64. 8 warps (4m x 2 k/d-half).
// ---------------------------------------------------------------------------
#define AQ_STR 132                        // uint32 per Q/K row
#define AOFF_Q 0
#define AOFF_K (128 * 528)                // 67584
#define AOFF_V (AOFF_K + 64 * 528)        // 101376
#define AOFF_P (AOFF_V + 256 * 144)       // 138240
#define AOFF_M (AOFF_P + 128 * 144)       // 156672  hm[128][2]
#define AOFF_L (AOFF_M + 1024)            // 157696  ll[128][2]
#define ATTN_SMEM (AOFF_L + 1024)         // 158720

__global__ __launch_bounds__(256) void attn_h_kernel()
{
    extern __shared__ char smn[];
    const uint32_t sb = cvta_shared(smn);
    const uint32_t* Qfu = (const uint32_t*)(smn + AOFF_Q);
    const uint32_t* Kfu = (const uint32_t*)(smn + AOFF_K);
    const uint32_t* Vtu = (const uint32_t*)(smn + AOFF_V);
    uint32_t* Ppu = (uint32_t*)(smn + AOFF_P);
    float* hm = (float*)(smn + AOFF_M);
    float* ll = (float*)(smn + AOFF_L);

    const int h  = blockIdx.y;
    const int hk = h >> 1;
    const int tid  = threadIdx.x;
    const int lane = tid & 31;
    const int wid  = tid >> 5;
    const int wm   = (wid & 3) * 32;
    const int wc   = wid >> 2;
    const int grp  = lane >> 2;
    const int qd   = lane & 3;

    const __half* Qh  = g_q  + (size_t)h  * S_LEN * HD;
    const __half* Kh  = g_k  + (size_t)hk * S_LEN * HD;
    const __half* Vth = g_vt + (size_t)hk * HD * S_LEN;

    const float LOG2E = 1.4426950408889634f;
    int rowsl[4];
#pragma unroll
    for (int sl = 0; sl < 4; sl++)
        rowsl[sl] = wm + (sl >> 1) * 16 + grp + (sl & 1) * 8;

    for (int half = 0; half < 2; half++) {
        const int qt = half ? (31 - blockIdx.x) : blockIdx.x;
        const int q0 = qt * 128;

        __syncthreads();
#pragma unroll
        for (int p = 0; p < 16; p++) {
            int idx = tid + p * 256;
            int row = idx >> 5, cc = idx & 31;
            cp16(sb + AOFF_Q + row * 528 + cc * 16,
                 &Qh[(size_t)(q0 + row) * HD + cc * 8]);
        }
        CP_COMMIT();

        float m_run[4], l_run[4], o[2][16][4];
#pragma unroll
        for (int sl = 0; sl < 4; sl++) { m_run[sl] = -3.0e38f; l_run[sl] = 0.f; }
#pragma unroll
        for (int mf = 0; mf < 2; mf++)
#pragma unroll
            for (int nt = 0; nt < 16; nt++)
#pragma unroll
                for (int r = 0; r < 4; r++) o[mf][nt][r] = 0.f;

        const int nkb = 2 * qt + 2;
        for (int kb = 0; kb < nkb; kb++) {
            const int k0 = kb * 64;
            __syncthreads();
#pragma unroll
            for (int p = 0; p < 8; p++) {
                int idx = tid + p * 256;
                int row = idx >> 5, cc = idx & 31;
                cp16(sb + AOFF_K + row * 528 + cc * 16,
                     &Kh[(size_t)(k0 + row) * HD + cc * 8]);
            }
            CP_COMMIT();
#pragma unroll
            for (int p = 0; p < 8; p++) {
                int idx = tid + p * 256;
                int row = idx >> 3, cc = idx & 7;
                cp16(sb + AOFF_V + row * 144 + cc * 16,
                     &Vth[(size_t)row * S_LEN + k0 + cc * 8]);
            }
            CP_COMMIT();
            CP_WAIT1();
            __syncthreads();

            // ---- QK ----
            float s[2][4][4];
#pragma unroll
            for (int mf = 0; mf < 2; mf++)
#pragma unroll
                for (int nt = 0; nt < 4; nt++)
#pragma unroll
                    for (int r = 0; r < 4; r++) s[mf][nt][r] = 0.f;
#pragma unroll 4
            for (int ks = 0; ks < 16; ks++) {
                const int kc = ks * 8 + qd;
                uint32_t a[2][4];
#pragma unroll
                for (int mf = 0; mf < 2; mf++) {
                    const int R = wm + mf * 16 + grp;
                    a[mf][0] = Qfu[R * AQ_STR + kc];
                    a[mf][1] = Qfu[(R + 8) * AQ_STR + kc];
                    a[mf][2] = Qfu[R * AQ_STR + kc + 4];
                    a[mf][3] = Qfu[(R + 8) * AQ_STR + kc + 4];
                }
#pragma unroll
                for (int nt = 0; nt < 4; nt++) {
                    const int nc = wc * 32 + nt * 8 + grp;
                    uint32_t b0 = Kfu[nc * AQ_STR + kc];
                    uint32_t b1 = Kfu[nc * AQ_STR + kc + 4];
#pragma unroll
                    for (int mf = 0; mf < 2; mf++)
                        MMA_F16(s[mf][nt], a[mf], b0, b1);
                }
            }

            // ---- softcap + causal + local row max ----
            float lm[4] = {-3.0e38f, -3.0e38f, -3.0e38f, -3.0e38f};
#pragma unroll
            for (int mf = 0; mf < 2; mf++)
#pragma unroll
                for (int nt = 0; nt < 4; nt++)
#pragma unroll
                    for (int cc = 0; cc < 4; cc++) {
                        float x = s[mf][nt][cc];
                        float u = x * 0.02f;
                        float u2 = u * u;
                        float val = x * (1.f + u2 * (-0.333333333f +
                                      u2 * (0.133333333f + u2 * -0.053968254f)));
                        if (u2 > 0.1225f) val = 50.f * tanhf(u);
                        int kcol = k0 + wc * 32 + nt * 8 + 2 * qd + (cc & 1);
                        int qrow = q0 + wm + mf * 16 + grp + (cc >> 1) * 8;
                        if (kcol > qrow) val = -1.0e30f;
                        s[mf][nt][cc] = val;
                        int sl = mf * 2 + (cc >> 1);
                        lm[sl] = fmaxf(lm[sl], val);
                    }
#pragma unroll
            for (int sl = 0; sl < 4; sl++) {
                lm[sl] = fmaxf(lm[sl], __shfl_xor_sync(0xffffffffu, lm[sl], 1));
                lm[sl] = fmaxf(lm[sl], __shfl_xor_sync(0xffffffffu, lm[sl], 2));
            }
            if (qd == 0) {
#pragma unroll
                for (int sl = 0; sl < 4; sl++)
                    hm[rowsl[sl] * 2 + wc] = lm[sl];
            }
            __syncthreads();

            // ---- combine max; exp; P; l ----
            float resc[4], ps[4];
#pragma unroll
            for (int sl = 0; sl < 4; sl++) {
                float om = fmaxf(hm[rowsl[sl] * 2], hm[rowsl[sl] * 2 + 1]);
                float mn = fmaxf(m_run[sl], om);
                resc[sl] = exp2f((m_run[sl] - mn) * LOG2E);
                m_run[sl] = mn;
                ps[sl] = 0.f;
            }
#pragma unroll
            for (int mf = 0; mf < 2; mf++) {
                const int sa = mf * 2, sb2 = mf * 2 + 1;
                const int R = wm + mf * 16 + grp;
#pragma unroll
                for (int nt = 0; nt < 4; nt++) {
                    float e0 = exp2f((s[mf][nt][0] - m_run[sa]) * LOG2E);
                    float e1 = exp2f((s[mf][nt][1] - m_run[sa]) * LOG2E);
                    float e2 = exp2f((s[mf][nt][2] - m_run[sb2]) * LOG2E);
                    float e3 = exp2f((s[mf][nt][3] - m_run[sb2]) * LOG2E);
                    ps[sa]  += e0 + e1;
                    ps[sb2] += e2 + e3;
                    Ppu[R * 36 + wc * 16 + nt * 4 + qd]       = pack2(e0, e1);
                    Ppu[(R + 8) * 36 + wc * 16 + nt * 4 + qd] = pack2(e2, e3);
                }
            }
#pragma unroll
            for (int sl = 0; sl < 4; sl++) {
                ps[sl] += __shfl_xor_sync(0xffffffffu, ps[sl], 1);
                ps[sl] += __shfl_xor_sync(0xffffffffu, ps[sl], 2);
                l_run[sl] = l_run[sl] * resc[sl] + ps[sl];
            }
#pragma unroll
            for (int mf = 0; mf < 2; mf++) {
                float r0 = resc[mf * 2], r1 = resc[mf * 2 + 1];
#pragma unroll
                for (int nt = 0; nt < 16; nt++) {
                    o[mf][nt][0] *= r0; o[mf][nt][1] *= r0;
                    o[mf][nt][2] *= r1; o[mf][nt][3] *= r1;
                }
            }
            CP_WAIT0();
            __syncthreads();

            // ---- PV ----
#pragma unroll
            for (int s4 = 0; s4 < 4; s4++) {
                const int kc = s4 * 8 + qd;
                uint32_t a[2][4];
#pragma unroll
                for (int mf = 0; mf < 2; mf++) {
                    const int R = wm + mf * 16 + grp;
                    a[mf][0] = Ppu[R * 36 + kc];
                    a[mf][1] = Ppu[(R + 8) * 36 + kc];
                    a[mf][2] = Ppu[R * 36 + kc + 4];
                    a[mf][3] = Ppu[(R + 8) * 36 + kc + 4];
                }
#pragma unroll
                for (int nt = 0; nt < 16; nt++) {
                    const int nc = wc * 128 + nt * 8 + grp;
                    uint32_t b0 = Vtu[nc * 36 + kc];
                    uint32_t b1 = Vtu[nc * 36 + kc + 4];
#pragma unroll
                    for (int mf = 0; mf < 2; mf++)
                        MMA_F16(o[mf][nt], a[mf], b0, b1);
                }
            }
        }

        // ---- epilogue: combine l halves, normalize, write fp16 ----
        if (qd == 0) {
#pragma unroll
            for (int sl = 0; sl < 4; sl++)
                ll[rowsl[sl] * 2 + wc] = l_run[sl];
        }
        __syncthreads();
        float li[4];
#pragma unroll
        for (int sl = 0; sl < 4; sl++)
            li[sl] = 1.f / (ll[rowsl[sl] * 2] + ll[rowsl[sl] * 2 + 1]);
#pragma unroll
        for (int mf = 0; mf < 2; mf++) {
            const int R = wm + mf * 16 + grp;
            float i0 = li[mf * 2], i1 = li[mf * 2 + 1];
#pragma unroll
            for (int nt = 0; nt < 16; nt++) {
                int col = h * HD + wc * 128 + nt * 8 + 2 * qd;
                *(uint32_t*)&g_attn[(size_t)(q0 + R) * 2048 + col] =
                    pack2(o[mf][nt][0] * i0, o[mf][nt][1] * i0);
                *(uint32_t*)&g_attn[(size_t)(q0 + R + 8) * 2048 + col] =
                    pack2(o[mf][nt][2] * i1, o[mf][nt][3] * i1);
            }
        }
    }
}

// ---------------------------------------------------------------------------
extern "C" void kernel_launch(void* const* d_in, const int* in_sizes, int n_in,
                              void* d_out, int out_size)
{
    const float* hs  = (const float*)d_in[0];
    // d_in[1] = attention_mask: pure causal (window >= S), recomputed in-kernel
    const void*  pos = d_in[2];
    const float* wq  = (const float*)d_in[3];
    const float* wk  = (const float*)d_in[4];
    const float* wv  = (const float*)d_in[5];
    const float* wo  = (const float*)d_in[6];
    float* out = (float*)d_out;

    __half *pq, *pk, *pvt, *pa, *pah, *pwqt, *pwkt, *pwvt, *pwot;
    cudaGetSymbolAddress((void**)&pq,   g_q);
    cudaGetSymbolAddress((void**)&pk,   g_k);
    cudaGetSymbolAddress((void**)&pvt,  g_vt);
    cudaGetSymbolAddress((void**)&pa,   g_attn);
    cudaGetSymbolAddress((void**)&pah,  g_ah);
    cudaGetSymbolAddress((void**)&pwqt, g_wqt);
    cudaGetSymbolAddress((void**)&pwkt, g_wkt);
    cudaGetSymbolAddress((void**)&pwvt, g_wvt);
    cudaGetSymbolAddress((void**)&pwot, g_wot);

    cudaFuncSetAttribute(gemm_h_kernel,
                         cudaFuncAttributeMaxDynamicSharedMemorySize, GH_SMEM);
    cudaFuncSetAttribute(attn_h_kernel,
                         cudaFuncAttributeMaxDynamicSharedMemorySize, ATTN_SMEM);

    const int n8 = (S_LEN * 2048) / 8;
    dim3 tb(32, 8);

    // prepasses
    invd_kernel<<<1, 128>>>();
    tohalf_kernel<<<(n8 + 255) / 256, 256>>>(hs, pah, n8);
    thalf_all_kernel<<<dim3(192, 64), tb>>>(wq, wk, wv, wo,
                                            pwqt, pwkt, pwvt, pwot);
    // fused QKV projection
    gemm_h_kernel<<<dim3(32, 32), 256, GH_SMEM>>>(
        pah, pwqt, pwkt, pwvt, pq, pk, pvt, nullptr, 1);
    // RoPE (+ fold attention scaling into q)
    rope_kernel<<<(S_LEN * 128) / 256, 256>>>(pos);
    // causal flash attention with tanh softcap (fp16, paired tiles)
    attn_h_kernel<<<dim3(16, NH), 256, ATTN_SMEM>>>();
    // output projection (reads fp16 attention output directly)
    gemm_h_kernel<<<dim3(16, 32), 256, GH_SMEM>>>(
        pa, pwot, nullptr, nullptr, nullptr, nullptr, nullptr, out, 0);
}

// round 13
// speedup vs baseline: 1.7654x; 1.0995x over previous
#include <cuda_runtime.h>
#include <cuda_fp16.h>
#include <math.h>
#include <stdint.h>

#define S_LEN 4096
#define NH 8
#define NKV 4
#define HD 256

// ---------------- scratch (allocation-free device globals) -----------------
__device__ __half g_q[(size_t)NH * S_LEN * HD];     // [h][s][d] fp16
__device__ __half g_k[(size_t)NKV * S_LEN * HD];    // [h][s][d] fp16
__device__ __half g_vt[(size_t)NKV * HD * S_LEN];   // [h][d][s] fp16 (transposed)
__device__ __half g_attn[(size_t)S_LEN * 2048];     // [s][h*HD+d] fp16
__device__ __half g_ah[(size_t)S_LEN * 2048];       // hs fp16
__device__ __half g_wqt[(size_t)2048 * 2048];       // weights [N][K] fp16
__device__ __half g_wkt[(size_t)1024 * 2048];
__device__ __half g_wvt[(size_t)1024 * 2048];
__device__ __half g_wot[(size_t)2048 * 2048];
__device__ double g_invd[128];                      // rope inv_freq table

__device__ __forceinline__ uint32_t cvta_shared(const void* p) {
    uint32_t a;
    asm("{ .reg .u64 t; cvta.to.shared.u64 t, %1; cvt.u32.u64 %0, t; }"
        : "=r"(a) : "l"(p));
    return a;
}

__device__ __forceinline__ void cp16(uint32_t dst, const void* src) {
    asm volatile("cp.async.cg.shared.global [%0], [%1], 16;"
                 :: "r"(dst), "l"(src));
}
#define CP_COMMIT() asm volatile("cp.async.commit_group;")
#define CP_WAIT0()  asm volatile("cp.async.wait_group 0;")
#define CP_WAIT1()  asm volatile("cp.async.wait_group 1;")

#define MMA_F16(C, A, B0, B1)                                               \
    asm volatile(                                                           \
        "mma.sync.aligned.m16n8k16.row.col.f32.f16.f16.f32 "                \
        "{%0,%1,%2,%3}, {%4,%5,%6,%7}, {%8,%9}, {%0,%1,%2,%3};"             \
        : "+f"((C)[0]), "+f"((C)[1]), "+f"((C)[2]), "+f"((C)[3])            \
        : "r"((A)[0]), "r"((A)[1]), "r"((A)[2]), "r"((A)[3]),               \
          "r"(B0), "r"(B1))

#define LDSM4(R, addr)                                                      \
    asm volatile("ldmatrix.sync.aligned.m8n8.x4.shared.b16 "                \
                 "{%0,%1,%2,%3}, [%4];"                                     \
        : "=r"((R)[0]), "=r"((R)[1]), "=r"((R)[2]), "=r"((R)[3])            \
        : "r"(addr))

__device__ __forceinline__ uint32_t pack2(float a, float b) {
    __half2 h = __floats2half2_rn(a, b);
    return *(uint32_t*)&h;
}

// ---------------------------------------------------------------------------
// Tiny prepass: inv_freq table (one fp64 exp per frequency, once).
// ---------------------------------------------------------------------------
__global__ void invd_kernel()
{
    int i = threadIdx.x;
    g_invd[i] = exp(-(double)i * (9.210340371976184 / 128.0));
}

// ---------------------------------------------------------------------------
// Prepass: fp32 -> fp16 (rn), 8 elems/thread.
// ---------------------------------------------------------------------------
__global__ void tohalf_kernel(const float* __restrict__ src,
                              __half* __restrict__ dst, int n8)
{
    int i = blockIdx.x * blockDim.x + threadIdx.x;
    if (i >= n8) return;
    float4 a = ((const float4*)src)[i * 2];
    float4 b = ((const float4*)src)[i * 2 + 1];
    uint4 o;
    o.x = pack2(a.x, a.y); o.y = pack2(a.z, a.w);
    o.z = pack2(b.x, b.y); o.w = pack2(b.z, b.w);
    ((uint4*)dst)[i] = o;
}

// ---------------------------------------------------------------------------
// Prepass: transpose + fp16 all four weights in ONE launch.
// ---------------------------------------------------------------------------
__global__ void thalf_all_kernel(const float* __restrict__ wq,
                                 const float* __restrict__ wk,
                                 const float* __restrict__ wv,
                                 const float* __restrict__ wo,
                                 __half* __restrict__ wqt,
                                 __half* __restrict__ wkt,
                                 __half* __restrict__ wvt,
                                 __half* __restrict__ wot)
{
    __shared__ float t[32][33];
    const int bx = blockIdx.x;
    const float* W;
    __half* Wt;
    int N, n0;
    if (bx < 64)       { W = wq; Wt = wqt; N = 2048; n0 = bx * 32; }
    else if (bx < 96)  { W = wk; Wt = wkt; N = 1024; n0 = (bx - 64) * 32; }
    else if (bx < 128) { W = wv; Wt = wvt; N = 1024; n0 = (bx - 96) * 32; }
    else               { W = wo; Wt = wot; N = 2048; n0 = (bx - 128) * 32; }
    const int k0 = blockIdx.y * 32;
    const int tx = threadIdx.x, ty = threadIdx.y;
#pragma unroll
    for (int j = 0; j < 4; j++)
        t[ty + 8 * j][tx] = W[(size_t)(k0 + ty + 8 * j) * N + n0 + tx];
    __syncthreads();
    const int nl = ty * 4 + (tx >> 3);
    const int kl = (tx & 7) * 4;
    uint2 o;
    o.x = pack2(t[kl + 0][nl], t[kl + 1][nl]);
    o.y = pack2(t[kl + 2][nl], t[kl + 3][nl]);
    *(uint2*)&Wt[(size_t)(n0 + nl) * 2048 + k0 + kl] = o;
}

// ---------------------------------------------------------------------------
// fp16 tensor-core GEMM with ldmatrix fragment loads.
// C[M,N] = A[M,2048] @ Wt[N,2048]^T, m16n8k16, 128x128 CTA tile, BK=64,
// 8 warps (4m x 2n), cp.async double-buffered.
// merged=1: fused QKV. bn<2048 -> q; <3072 -> k; else v transposed [h][d][s].
// ---------------------------------------------------------------------------
#define GH_PLANE 18432                   // 128 rows * 144 B
#define GH_STAGE (2 * GH_PLANE)
#define GH_SMEM  (2 * GH_STAGE)          // 73728 B

__global__ __launch_bounds__(256, 2) void gemm_h_kernel(
    const __half* __restrict__ A,
    const __half* __restrict__ B0t, const __half* __restrict__ B1t,
    const __half* __restrict__ B2t,
    __half* __restrict__ Cq, __half* __restrict__ Ck, __half* __restrict__ Cvt,
    float* __restrict__ Cplain, int merged)
{
    extern __shared__ char gsm[];
    const uint32_t smem_base = cvta_shared(gsm);

    const int tid  = threadIdx.x;
    const int lane = tid & 31;
    const int wid  = tid >> 5;
    const int wm   = (wid & 3) * 32;
    const int wn   = (wid >> 2) * 64;
    const int bm   = blockIdx.y * 128;
    const int bn   = blockIdx.x * 128;
    const int grp  = lane >> 2;
    const int qd   = lane & 3;
    const int mi   = lane >> 3;           // ldmatrix matrix index
    const int r8   = lane & 7;            // ldmatrix row-in-matrix

    // ldmatrix per-lane address offsets (within a stage)
    const uint32_t aoff = (uint32_t)(wm + (mi & 1) * 8 + r8) * 144 + (mi >> 1) * 16;
    const uint32_t boff = (uint32_t)GH_PLANE +
                          (uint32_t)(wn + (mi >> 1) * 8 + r8) * 144 + (mi & 1) * 16;

    const __half* Bt;
    int nb, head = 0, colb0 = 0, region = 0;
    if (merged) {
        if (bn < 2048)      { Bt = B0t; nb = bn;        region = 0; }
        else if (bn < 3072) { Bt = B1t; nb = bn - 2048; region = 1; }
        else                { Bt = B2t; nb = bn - 3072; region = 2; }
        head = nb >> 8;
        colb0 = nb & 255;
    } else {
        Bt = B0t; nb = bn;
    }

    auto load_stage = [&](int chunk, int st) {
        const int k0 = chunk * 64;
        const uint32_t sb = smem_base + st * GH_STAGE;
#pragma unroll
        for (int p = 0; p < 4; p++) {
            int idx = tid + p * 256;
            int row = idx >> 3, c = idx & 7;
            cp16(sb + row * 144 + c * 16,
                 &A[(size_t)(bm + row) * 2048 + k0 + c * 8]);
            cp16(sb + GH_PLANE + row * 144 + c * 16,
                 &Bt[(size_t)(nb + row) * 2048 + k0 + c * 8]);
        }
        CP_COMMIT();
    };

    float c[2][8][4];
#pragma unroll
    for (int mf = 0; mf < 2; mf++)
#pragma unroll
        for (int nt = 0; nt < 8; nt++)
#pragma unroll
            for (int r = 0; r < 4; r++) c[mf][nt][r] = 0.f;

    load_stage(0, 0);

    for (int i = 0; i < 32; i++) {
        const int st = i & 1;
        CP_WAIT0();
        __syncthreads();
        if (i + 1 < 32) load_stage(i + 1, st ^ 1);

        const uint32_t stb = smem_base + st * GH_STAGE;
#pragma unroll
        for (int s = 0; s < 4; s++) {
            uint32_t a[2][4];
            LDSM4(a[0], stb + aoff + s * 32);
            LDSM4(a[1], stb + aoff + 16 * 144 + s * 32);
#pragma unroll
            for (int ntp = 0; ntp < 4; ntp++) {
                uint32_t b[4];
                LDSM4(b, stb + boff + ntp * (16 * 144) + s * 32);
                MMA_F16(c[0][2 * ntp],     a[0], b[0], b[1]);
                MMA_F16(c[1][2 * ntp],     a[1], b[0], b[1]);
                MMA_F16(c[0][2 * ntp + 1], a[0], b[2], b[3]);
                MMA_F16(c[1][2 * ntp + 1], a[1], b[2], b[3]);
            }
        }
        __syncthreads();
    }

    const int m0 = bm + wm + grp;
    const int n0 = wn + 2 * qd;
    if (merged) {
        if (region < 2) {
            __half* Cp = (region == 0) ? Cq : Ck;
            const size_t hbase = (size_t)head * ((size_t)S_LEN * HD) + colb0;
#pragma unroll
            for (int mf = 0; mf < 2; mf++)
#pragma unroll
                for (int nt = 0; nt < 8; nt++) {
                    int m = m0 + mf * 16;
                    int ncol = n0 + nt * 8;
                    *(uint32_t*)&Cp[hbase + (size_t)m * HD + ncol] =
                        pack2(c[mf][nt][0], c[mf][nt][1]);
                    *(uint32_t*)&Cp[hbase + (size_t)(m + 8) * HD + ncol] =
                        pack2(c[mf][nt][2], c[mf][nt][3]);
                }
        } else {
            const size_t vbase = (size_t)head * ((size_t)HD * S_LEN);
#pragma unroll
            for (int mf = 0; mf < 2; mf++)
#pragma unroll
                for (int nt = 0; nt < 8; nt++) {
                    int m = m0 + mf * 16;
                    int d = colb0 + n0 + nt * 8;
                    Cvt[vbase + (size_t)d * S_LEN + m]           = __float2half_rn(c[mf][nt][0]);
                    Cvt[vbase + (size_t)(d + 1) * S_LEN + m]     = __float2half_rn(c[mf][nt][1]);
                    Cvt[vbase + (size_t)d * S_LEN + m + 8]       = __float2half_rn(c[mf][nt][2]);
                    Cvt[vbase + (size_t)(d + 1) * S_LEN + m + 8] = __float2half_rn(c[mf][nt][3]);
                }
        }
    } else {
#pragma unroll
        for (int mf = 0; mf < 2; mf++)
#pragma unroll
            for (int nt = 0; nt < 8; nt++) {
                int m = m0 + mf * 16;
                int n = bn + n0 + nt * 8;
                *(float2*)&Cplain[(size_t)m * 2048 + n] =
                    make_float2(c[mf][nt][0], c[mf][nt][1]);
                *(float2*)&Cplain[(size_t)(m + 8) * 2048 + n] =
                    make_float2(c[mf][nt][2], c[mf][nt][3]);
            }
    }
}

// ---------------------------------------------------------------------------
// RoPE on fp16 q/k. inv_freq from table; range reduction via DMUL.
// ---------------------------------------------------------------------------
__global__ void rope_kernel(const void* __restrict__ pos_raw)
{
    int idx = blockIdx.x * blockDim.x + threadIdx.x;
    if (idx >= S_LEN * 128) return;
    int i = idx & 127;
    int s = idx >> 7;

    const int* p32 = (const int*)pos_raw;
    long long pll = (p32[1] == 0) ? ((const long long*)pos_raw)[s]
                                  : (long long)p32[s];
    float p = (float)pll;

    float f = (float)((double)p * g_invd[i]);   // fp32 freq like reference
    const double TWO_PI     = 6.283185307179586476925287;
    const double INV_TWO_PI = 0.15915494309189533576888;
    double r = (double)f;
    r -= TWO_PI * floor(r * INV_TWO_PI);
    float sv = sinf((float)r);
    float cv = cosf((float)r);

#pragma unroll
    for (int h = 0; h < NH; h++) {
        __half* base = g_q + ((size_t)h * S_LEN + s) * HD;
        float x1 = __half2float(base[i]), x2 = __half2float(base[i + 128]);
        base[i]       = __float2half_rn((x1 * cv - x2 * sv) * 0.0625f);
        base[i + 128] = __float2half_rn((x2 * cv + x1 * sv) * 0.0625f);
    }
#pragma unroll
    for (int h = 0; h < NKV; h++) {
        __half* base = g_k + ((size_t)h * S_LEN + s) * HD;
        float x1 = __half2float(base[i]), x2 = __half2float(base[i + 128]);
        base[i]       = __float2half_rn(x1 * cv - x2 * sv);
        base[i + 128] = __float2half_rn(x2 * cv + x1 * sv);
    }
}

// ---------------------------------------------------------------------------
// fp16 flash attention, ldmatrix fragment loads, in-register softmax.
// Grid (16, 8) = 128 blocks, block = q-tiles qt & 31-qt (128 rows each),
// 66 uniform k-blocks of 64. 8 warps (4m x 2 k/d-half).
// ---------------------------------------------------------------------------
#define AQ_STR 132                        // uint32 per Q/K row
#define AOFF_Q 0
#define AOFF_K (128 * 528)                // 67584
#define AOFF_V (AOFF_K + 64 * 528)        // 101376
#define AOFF_P (AOFF_V + 256 * 144)       // 138240
#define AOFF_M (AOFF_P + 128 * 144)       // 156672  hm[128][2]
#define AOFF_L (AOFF_M + 1024)            // 157696  ll[128][2]
#define ATTN_SMEM (AOFF_L + 1024)         // 158720

__global__ __launch_bounds__(256) void attn_h_kernel()
{
    extern __shared__ char smn[];
    const uint32_t sb = cvta_shared(smn);
    uint32_t* Ppu = (uint32_t*)(smn + AOFF_P);
    float* hm = (float*)(smn + AOFF_M);
    float* ll = (float*)(smn + AOFF_L);

    const int h  = blockIdx.y;
    const int hk = h >> 1;
    const int tid  = threadIdx.x;
    const int lane = tid & 31;
    const int wid  = tid >> 5;
    const int wm   = (wid & 3) * 32;
    const int wc   = wid >> 2;
    const int grp  = lane >> 2;
    const int qd   = lane & 3;
    const int mi   = lane >> 3;
    const int r8   = lane & 7;

    // ldmatrix per-lane bases
    const uint32_t qBase = sb + AOFF_Q +
        (uint32_t)(wm + (mi & 1) * 8 + r8) * 528 + (mi >> 1) * 16;
    const uint32_t kBase = sb + AOFF_K +
        (uint32_t)(wc * 32 + (mi >> 1) * 8 + r8) * 528 + (mi & 1) * 16;
    const uint32_t pBase = sb + AOFF_P +
        (uint32_t)(wm + (mi & 1) * 8 + r8) * 144 + (mi >> 1) * 16;
    const uint32_t vBase = sb + AOFF_V +
        (uint32_t)(wc * 128 + (mi >> 1) * 8 + r8) * 144 + (mi & 1) * 16;

    const __half* Qh  = g_q  + (size_t)h  * S_LEN * HD;
    const __half* Kh  = g_k  + (size_t)hk * S_LEN * HD;
    const __half* Vth = g_vt + (size_t)hk * HD * S_LEN;

    const float LOG2E = 1.4426950408889634f;
    int rowsl[4];
#pragma unroll
    for (int sl = 0; sl < 4; sl++)
        rowsl[sl] = wm + (sl >> 1) * 16 + grp + (sl & 1) * 8;

    for (int half = 0; half < 2; half++) {
        const int qt = half ? (31 - blockIdx.x) : blockIdx.x;
        const int q0 = qt * 128;

        __syncthreads();
#pragma unroll
        for (int p = 0; p < 16; p++) {
            int idx = tid + p * 256;
            int row = idx >> 5, cc = idx & 31;
            cp16(sb + AOFF_Q + row * 528 + cc * 16,
                 &Qh[(size_t)(q0 + row) * HD + cc * 8]);
        }
        CP_COMMIT();

        float m_run[4], l_run[4], o[2][16][4];
#pragma unroll
        for (int sl = 0; sl < 4; sl++) { m_run[sl] = -3.0e38f; l_run[sl] = 0.f; }
#pragma unroll
        for (int mf = 0; mf < 2; mf++)
#pragma unroll
            for (int nt = 0; nt < 16; nt++)
#pragma unroll
                for (int r = 0; r < 4; r++) o[mf][nt][r] = 0.f;

        const int nkb = 2 * qt + 2;
        for (int kb = 0; kb < nkb; kb++) {
            const int k0 = kb * 64;
            __syncthreads();
#pragma unroll
            for (int p = 0; p < 8; p++) {
                int idx = tid + p * 256;
                int row = idx >> 5, cc = idx & 31;
                cp16(sb + AOFF_K + row * 528 + cc * 16,
                     &Kh[(size_t)(k0 + row) * HD + cc * 8]);
            }
            CP_COMMIT();
#pragma unroll
            for (int p = 0; p < 8; p++) {
                int idx = tid + p * 256;
                int row = idx >> 3, cc = idx & 7;
                cp16(sb + AOFF_V + row * 144 + cc * 16,
                     &Vth[(size_t)row * S_LEN + k0 + cc * 8]);
            }
            CP_COMMIT();
            CP_WAIT1();
            __syncthreads();

            // ---- QK (ldmatrix) ----
            float s[2][4][4];
#pragma unroll
            for (int mf = 0; mf < 2; mf++)
#pragma unroll
                for (int nt = 0; nt < 4; nt++)
#pragma unroll
                    for (int r = 0; r < 4; r++) s[mf][nt][r] = 0.f;
#pragma unroll 4
            for (int ks = 0; ks < 16; ks++) {
                uint32_t a[2][4];
                LDSM4(a[0], qBase + ks * 32);
                LDSM4(a[1], qBase + 16 * 528 + ks * 32);
#pragma unroll
                for (int ntp = 0; ntp < 2; ntp++) {
                    uint32_t b[4];
                    LDSM4(b, kBase + ntp * (16 * 528) + ks * 32);
                    MMA_F16(s[0][2 * ntp],     a[0], b[0], b[1]);
                    MMA_F16(s[1][2 * ntp],     a[1], b[0], b[1]);
                    MMA_F16(s[0][2 * ntp + 1], a[0], b[2], b[3]);
                    MMA_F16(s[1][2 * ntp + 1], a[1], b[2], b[3]);
                }
            }

            // ---- softcap + causal + local row max ----
            float lm[4] = {-3.0e38f, -3.0e38f, -3.0e38f, -3.0e38f};
#pragma unroll
            for (int mf = 0; mf < 2; mf++)
#pragma unroll
                for (int nt = 0; nt < 4; nt++)
#pragma unroll
                    for (int cc = 0; cc < 4; cc++) {
                        float x = s[mf][nt][cc];
                        float u = x * 0.02f;
                        float u2 = u * u;
                        float val = x * (1.f + u2 * (-0.333333333f +
                                      u2 * (0.133333333f + u2 * -0.053968254f)));
                        if (u2 > 0.1225f) val = 50.f * tanhf(u);
                        int kcol = k0 + wc * 32 + nt * 8 + 2 * qd + (cc & 1);
                        int qrow = q0 + wm + mf * 16 + grp + (cc >> 1) * 8;
                        if (kcol > qrow) val = -1.0e30f;
                        s[mf][nt][cc] = val;
                        int sl = mf * 2 + (cc >> 1);
                        lm[sl] = fmaxf(lm[sl], val);
                    }
#pragma unroll
            for (int sl = 0; sl < 4; sl++) {
                lm[sl] = fmaxf(lm[sl], __shfl_xor_sync(0xffffffffu, lm[sl], 1));
                lm[sl] = fmaxf(lm[sl], __shfl_xor_sync(0xffffffffu, lm[sl], 2));
            }
            if (qd == 0) {
#pragma unroll
                for (int sl = 0; sl < 4; sl++)
                    hm[rowsl[sl] * 2 + wc] = lm[sl];
            }
            __syncthreads();

            // ---- combine max; exp; P; l ----
            float resc[4], ps[4];
#pragma unroll
            for (int sl = 0; sl < 4; sl++) {
                float om = fmaxf(hm[rowsl[sl] * 2], hm[rowsl[sl] * 2 + 1]);
                float mn = fmaxf(m_run[sl], om);
                resc[sl] = exp2f((m_run[sl] - mn) * LOG2E);
                m_run[sl] = mn;
                ps[sl] = 0.f;
            }
#pragma unroll
            for (int mf = 0; mf < 2; mf++) {
                const int sa = mf * 2, sb2 = mf * 2 + 1;
                const int R = wm + mf * 16 + grp;
#pragma unroll
                for (int nt = 0; nt < 4; nt++) {
                    float e0 = exp2f((s[mf][nt][0] - m_run[sa]) * LOG2E);
                    float e1 = exp2f((s[mf][nt][1] - m_run[sa]) * LOG2E);
                    float e2 = exp2f((s[mf][nt][2] - m_run[sb2]) * LOG2E);
                    float e3 = exp2f((s[mf][nt][3] - m_run[sb2]) * LOG2E);
                    ps[sa]  += e0 + e1;
                    ps[sb2] += e2 + e3;
                    Ppu[R * 36 + wc * 16 + nt * 4 + qd]       = pack2(e0, e1);
                    Ppu[(R + 8) * 36 + wc * 16 + nt * 4 + qd] = pack2(e2, e3);
                }
            }
#pragma unroll
            for (int sl = 0; sl < 4; sl++) {
                ps[sl] += __shfl_xor_sync(0xffffffffu, ps[sl], 1);
                ps[sl] += __shfl_xor_sync(0xffffffffu, ps[sl], 2);
                l_run[sl] = l_run[sl] * resc[sl] + ps[sl];
            }
#pragma unroll
            for (int mf = 0; mf < 2; mf++) {
                float r0 = resc[mf * 2], r1 = resc[mf * 2 + 1];
#pragma unroll
                for (int nt = 0; nt < 16; nt++) {
                    o[mf][nt][0] *= r0; o[mf][nt][1] *= r0;
                    o[mf][nt][2] *= r1; o[mf][nt][3] *= r1;
                }
            }
            CP_WAIT0();
            __syncthreads();

            // ---- PV (ldmatrix) ----
#pragma unroll
            for (int s4 = 0; s4 < 4; s4++) {
                uint32_t a[2][4];
                LDSM4(a[0], pBase + s4 * 32);
                LDSM4(a[1], pBase + 16 * 144 + s4 * 32);
#pragma unroll
                for (int ntp = 0; ntp < 8; ntp++) {
                    uint32_t b[4];
                    LDSM4(b, vBase + ntp * (16 * 144) + s4 * 32);
                    MMA_F16(o[0][2 * ntp],     a[0], b[0], b[1]);
                    MMA_F16(o[1][2 * ntp],     a[1], b[0], b[1]);
                    MMA_F16(o[0][2 * ntp + 1], a[0], b[2], b[3]);
                    MMA_F16(o[1][2 * ntp + 1], a[1], b[2], b[3]);
                }
            }
        }

        // ---- epilogue: combine l halves, normalize, write fp16 ----
        if (qd == 0) {
#pragma unroll
            for (int sl = 0; sl < 4; sl++)
                ll[rowsl[sl] * 2 + wc] = l_run[sl];
        }
        __syncthreads();
        float li[4];
#pragma unroll
        for (int sl = 0; sl < 4; sl++)
            li[sl] = 1.f / (ll[rowsl[sl] * 2] + ll[rowsl[sl] * 2 + 1]);
#pragma unroll
        for (int mf = 0; mf < 2; mf++) {
            const int R = wm + mf * 16 + grp;
            float i0 = li[mf * 2], i1 = li[mf * 2 + 1];
#pragma unroll
            for (int nt = 0; nt < 16; nt++) {
                int col = h * HD + wc * 128 + nt * 8 + 2 * qd;
                *(uint32_t*)&g_attn[(size_t)(q0 + R) * 2048 + col] =
                    pack2(o[mf][nt][0] * i0, o[mf][nt][1] * i0);
                *(uint32_t*)&g_attn[(size_t)(q0 + R + 8) * 2048 + col] =
                    pack2(o[mf][nt][2] * i1, o[mf][nt][3] * i1);
            }
        }
    }
}

// ---------------------------------------------------------------------------
extern "C" void kernel_launch(void* const* d_in, const int* in_sizes, int n_in,
                              void* d_out, int out_size)
{
    const float* hs  = (const float*)d_in[0];
    // d_in[1] = attention_mask: pure causal (window >= S), recomputed in-kernel
    const void*  pos = d_in[2];
    const float* wq  = (const float*)d_in[3];
    const float* wk  = (const float*)d_in[4];
    const float* wv  = (const float*)d_in[5];
    const float* wo  = (const float*)d_in[6];
    float* out = (float*)d_out;

    __half *pq, *pk, *pvt, *pa, *pah, *pwqt, *pwkt, *pwvt, *pwot;
    cudaGetSymbolAddress((void**)&pq,   g_q);
    cudaGetSymbolAddress((void**)&pk,   g_k);
    cudaGetSymbolAddress((void**)&pvt,  g_vt);
    cudaGetSymbolAddress((void**)&pa,   g_attn);
    cudaGetSymbolAddress((void**)&pah,  g_ah);
    cudaGetSymbolAddress((void**)&pwqt, g_wqt);
    cudaGetSymbolAddress((void**)&pwkt, g_wkt);
    cudaGetSymbolAddress((void**)&pwvt, g_wvt);
    cudaGetSymbolAddress((void**)&pwot, g_wot);

    cudaFuncSetAttribute(gemm_h_kernel,
                         cudaFuncAttributeMaxDynamicSharedMemorySize, GH_SMEM);
    cudaFuncSetAttribute(attn_h_kernel,
                         cudaFuncAttributeMaxDynamicSharedMemorySize, ATTN_SMEM);

    const int n8 = (S_LEN * 2048) / 8;
    dim3 tb(32, 8);

    // prepasses
    invd_kernel<<<1, 128>>>();
    tohalf_kernel<<<(n8 + 255) / 256, 256>>>(hs, pah, n8);
    thalf_all_kernel<<<dim3(192, 64), tb>>>(wq, wk, wv, wo,
                                            pwqt, pwkt, pwvt, pwot);
    // fused QKV projection
    gemm_h_kernel<<<dim3(32, 32), 256, GH_SMEM>>>(
        pah, pwqt, pwkt, pwvt, pq, pk, pvt, nullptr, 1);
    // RoPE (+ fold attention scaling into q)
    rope_kernel<<<(S_LEN * 128) / 256, 256>>>(pos);
    // causal flash attention with tanh softcap (fp16, paired tiles)
    attn_h_kernel<<<dim3(16, NH), 256, ATTN_SMEM>>>();
    // output projection (reads fp16 attention output directly)
    gemm_h_kernel<<<dim3(16, 32), 256, GH_SMEM>>>(
        pa, pwot, nullptr, nullptr, nullptr, nullptr, nullptr, out, 0);
}